// round 9
// baseline (speedup 1.0000x reference)
#include <cuda_runtime.h>
#include <cuda_bf16.h>
#include <cstdint>

// Problem constants
#define NR   16384
#define DIN  1024
#define DH   4096
#define DZ   256
#define KCB  4096
#define RESCUE_CAP 4096

// ===================== scratch (device globals) ==============================
__device__ __nv_bfloat16 g_xs [3u * NR * DIN];
__device__ __nv_bfloat16 g_w1s[3u * DH * DIN];
__device__ __nv_bfloat16 g_w2s[3u * DH * DH];
__device__ __nv_bfloat16 g_w3s[3u * DZ * DH];
__device__ __nv_bfloat16 g_h1s[3ull * NR * DH];   // limbs (H rows valid)
__device__ __nv_bfloat16 g_h2s[3ull * NR * DH];
__device__ float g_h1f[(size_t)NR * DH];          // fp32 (F rows valid)
__device__ float g_h2f[(size_t)NR * DH];
__device__ float g_z [NR * DZ];
__device__ float g_znorm[NR];
__device__ float g_cnorm[KCB];
__device__ float g_pval [4 * NR];
__device__ float g_pval2[4 * NR];
__device__ int   g_pidx[4 * NR];
__device__ float g_minval[NR];
__device__ int   g_minidx[NR];
__device__ int   g_flagcnt;
__device__ int   g_flaglist[RESCUE_CAP];

// ===================== helpers ===============================================
__device__ __forceinline__ uint32_t smem_to_u32(const void* smem_ptr) {
    uint32_t addr;
    asm("{ .reg .u64 tmp; cvta.to.shared.u64 tmp, %1; cvt.u32.u64 %0, tmp; }"
        : "=r"(addr) : "l"(smem_ptr));
    return addr;
}
__device__ __forceinline__ void split3(float v, __nv_bfloat16& h, __nv_bfloat16& m,
                                       __nv_bfloat16& l) {
    h = __float2bfloat16(v);
    float r = v - __bfloat162float(h);
    m = __float2bfloat16(r);
    float r2 = r - __bfloat162float(m);
    l = __float2bfloat16(r2);
}
__device__ __forceinline__ uint32_t pk2(__nv_bfloat16 a, __nv_bfloat16 b) {
    return (uint32_t)__bfloat16_as_ushort(a) | ((uint32_t)__bfloat16_as_ushort(b) << 16);
}

#define LDMX4(r, addr) \
    asm volatile("ldmatrix.sync.aligned.m8n8.x4.shared.b16 {%0,%1,%2,%3}, [%4];" \
        : "=r"((r)[0]), "=r"((r)[1]), "=r"((r)[2]), "=r"((r)[3]) : "r"(addr))

#define MMA16816(d, a, b0, b1) \
    asm volatile("mma.sync.aligned.m16n8k16.row.col.f32.bf16.bf16.f32 " \
        "{%0,%1,%2,%3}, {%4,%5,%6,%7}, {%8,%9}, {%0,%1,%2,%3};" \
        : "+f"((d)[0]), "+f"((d)[1]), "+f"((d)[2]), "+f"((d)[3]) \
        : "r"((a)[0]), "r"((a)[1]), "r"((a)[2]), "r"((a)[3]), "r"(b0), "r"(b1))

// ===================== split kernels =========================================
__global__ void split_kernel(const float* __restrict__ in, __nv_bfloat16* __restrict__ out,
                             size_t n, size_t ps)
{
    size_t i = ((size_t)blockIdx.x * blockDim.x + threadIdx.x) * 4;
    if (i >= n) return;
    float4 v = *(const float4*)(in + i);
    __nv_bfloat16 h[4], m[4], l[4];
    split3(v.x, h[0], m[0], l[0]);
    split3(v.y, h[1], m[1], l[1]);
    split3(v.z, h[2], m[2], l[2]);
    split3(v.w, h[3], m[3], l[3]);
    *(uint2*)(out + i)        = make_uint2(pk2(h[0],h[1]), pk2(h[2],h[3]));
    *(uint2*)(out + ps + i)   = make_uint2(pk2(m[0],m[1]), pk2(m[2],m[3]));
    *(uint2*)(out + 2*ps + i) = make_uint2(pk2(l[0],l[1]), pk2(l[2],l[3]));
}

// split + transpose weight W[K][N] fp32 -> out[3][N][K] bf16 limbs
__global__ void splitT_kernel(const float* __restrict__ W, __nv_bfloat16* __restrict__ out,
                              int K, int N, size_t ps)
{
    __shared__ float tile[32][33];
    int k0 = blockIdx.y * 32, n0 = blockIdx.x * 32;
    int tx = threadIdx.x, ty = threadIdx.y;   // 32 x 8
#pragma unroll
    for (int dy = 0; dy < 32; dy += 8)
        tile[ty + dy][tx] = W[(size_t)(k0 + ty + dy) * N + n0 + tx];
    __syncthreads();
#pragma unroll
    for (int dy = 0; dy < 32; dy += 8) {
        int n = n0 + ty + dy, k = k0 + tx;
        float v = tile[tx][ty + dy];
        __nv_bfloat16 h, m, l;
        split3(v, h, m, l);
        size_t off = (size_t)n * K + k;
        out[off]        = h;
        out[ps + off]   = m;
        out[2*ps + off] = l;
    }
}

// ===================== warp-specialized dual-pipe GEMM =======================
// CTA = 256 rows x 128 cols, BK=32, 512 threads.
// Warps 0-7  (F): rows 0-127, exact fp32 FFMA (fma pipe).
// Warps 8-15 (H): rows 128-255, bf16x3 limbs via mma.sync (tensor pipe).
// Stage smem: A_f32[128][36f pitch144B] | B_f32[32][132f pitch528B]
//           | A-limbs 3x(128x80B)       | B-limbs 3x(128x80B)
#define AN_OFF    0
#define BF_OFF    18432
#define AL_OFF    35328
#define BL_OFF    66048
#define HSTG      96768
#define HYB_SMEM  (2 * HSTG)   // 193536

__global__ __launch_bounds__(512, 1)
void gemm_hybrid_kernel(const float* __restrict__ Af,      // fp32 A [M][Kg] (F rows valid)
                        const __nv_bfloat16* __restrict__ Ap, size_t aps,   // A limbs [M][Kg]
                        const float* __restrict__ Wf,      // fp32 W [Kg][Ng]
                        const __nv_bfloat16* __restrict__ Bp, size_t bps,   // W^T limbs [N][Kg]
                        const float* __restrict__ bias,
                        float* __restrict__ outF,          // fp32 out (F rows; H too if !outp)
                        __nv_bfloat16* __restrict__ outp, size_t ops,       // limb out (H rows)
                        int Kg, int Ng, int relu)
{
    extern __shared__ char smem[];
    const uint32_t sb = smem_to_u32(smem);
    const int tid = threadIdx.x;
    const int wid = tid >> 5, lane = tid & 31;
    const int m0 = blockIdx.y * 256, n0 = blockIdx.x * 128;
    const int nStages = Kg >> 5;

    auto load_stage = [&](int s) {
        const uint32_t dstb = sb + (uint32_t)(s & 1) * HSTG;
        const int k0 = s << 5;
#pragma unroll
        for (int t = 0; t < 10; t++) {
            int id = tid + t * 512;             // 0..5119
            if (id < 1024) {                    // A fp32: 128 rows x 8 chunks
                int r = id >> 3, c = id & 7;
                const float* src = Af + (size_t)(m0 + r) * Kg + k0 + c * 4;
                uint32_t dst = dstb + AN_OFF + (uint32_t)(r * 144 + c * 16);
                asm volatile("cp.async.cg.shared.global [%0], [%1], 16;"
                             :: "r"(dst), "l"(src) : "memory");
            } else if (id < 2048) {             // B fp32: 32 k-rows x 32 chunks
                int j = id - 1024;
                int kk = j >> 5, c = j & 31;
                const float* src = Wf + (size_t)(k0 + kk) * Ng + n0 + c * 4;
                uint32_t dst = dstb + BF_OFF + (uint32_t)(kk * 528 + c * 16);
                asm volatile("cp.async.cg.shared.global [%0], [%1], 16;"
                             :: "r"(dst), "l"(src) : "memory");
            } else if (id < 3584) {             // A limbs: 3 x 128 x 4 chunks
                int j = id - 2048;
                int p = j >> 9, rem = j & 511;
                int r = rem >> 2, c = rem & 3;
                const __nv_bfloat16* src = Ap + (size_t)p * aps
                                         + (size_t)(m0 + 128 + r) * Kg + k0 + c * 8;
                uint32_t dst = dstb + AL_OFF + (uint32_t)(p * 10240 + r * 80 + c * 16);
                asm volatile("cp.async.cg.shared.global [%0], [%1], 16;"
                             :: "r"(dst), "l"(src) : "memory");
            } else {                            // B limbs: 3 x 128 x 4 chunks
                int j = id - 3584;
                int p = j >> 9, rem = j & 511;
                int r = rem >> 2, c = rem & 3;
                const __nv_bfloat16* src = Bp + (size_t)p * bps
                                         + (size_t)(n0 + r) * Kg + k0 + c * 8;
                uint32_t dst = dstb + BL_OFF + (uint32_t)(p * 10240 + r * 80 + c * 16);
                asm volatile("cp.async.cg.shared.global [%0], [%1], 16;"
                             :: "r"(dst), "l"(src) : "memory");
            }
        }
        asm volatile("cp.async.commit_group;" ::: "memory");
    };

    // F state
    const int tm = (tid & 255) >> 4, tn = tid & 15;
    float facc[8][8];
    // H state
    const int hw = wid - 8;
    const int wm = hw >> 2, wn = hw & 3;
    const int brow  = (lane & 7) + ((lane >> 3) & 1) * 8;
    const int chalf = lane >> 4;
    float hacc[4][4][4];
    const int PA[6] = {0, 0, 1, 0, 2, 1};
    const int PB[6] = {0, 1, 0, 2, 0, 1};

    if (wid < 8) {
#pragma unroll
        for (int i = 0; i < 8; i++)
#pragma unroll
            for (int j = 0; j < 8; j++) facc[i][j] = 0.f;
    } else {
#pragma unroll
        for (int i = 0; i < 4; i++)
#pragma unroll
            for (int j = 0; j < 4; j++)
#pragma unroll
                for (int q = 0; q < 4; q++) hacc[i][j][q] = 0.f;
    }

    load_stage(0);
    if (nStages > 1) load_stage(1);

    for (int it = 0; it < nStages; it++) {
        if (it + 1 < nStages) asm volatile("cp.async.wait_group 1;" ::: "memory");
        else                  asm volatile("cp.async.wait_group 0;" ::: "memory");
        __syncthreads();

        const uint32_t stb = sb + (uint32_t)(it & 1) * HSTG;

        if (wid < 8) {
            // ---- F: exact fp32, 8x8 microtile, vector LDS ----
            const char* smem_st = smem + (size_t)(it & 1) * HSTG;
#pragma unroll 1
            for (int g = 0; g < 8; g++) {
                float4 bq0[4], bq1[4];
#pragma unroll
                for (int q = 0; q < 4; q++) {
                    const float* br = (const float*)(smem_st + BF_OFF + (g*4 + q) * 528);
                    bq0[q] = *(const float4*)(br + tn * 8);
                    bq1[q] = *(const float4*)(br + tn * 8 + 4);
                }
#pragma unroll
                for (int i = 0; i < 8; i++) {
                    float4 a = *(const float4*)(smem_st + AN_OFF + (tm*8 + i) * 144 + g * 16);
#pragma unroll
                    for (int q = 0; q < 4; q++) {
                        float av = (q == 0) ? a.x : (q == 1) ? a.y : (q == 2) ? a.z : a.w;
                        facc[i][0] += av * bq0[q].x;
                        facc[i][1] += av * bq0[q].y;
                        facc[i][2] += av * bq0[q].z;
                        facc[i][3] += av * bq0[q].w;
                        facc[i][4] += av * bq1[q].x;
                        facc[i][5] += av * bq1[q].y;
                        facc[i][6] += av * bq1[q].z;
                        facc[i][7] += av * bq1[q].w;
                    }
                }
            }
        } else {
            // ---- H: bf16x3 mma.sync (R5 body) ----
            const uint32_t sA = stb + AL_OFF;
            const uint32_t sB = stb + BL_OFF;
#pragma unroll
            for (int kk2 = 0; kk2 < 2; kk2++) {
                uint32_t Bfr[3][2][4];
#pragma unroll
                for (int p = 0; p < 3; p++)
#pragma unroll
                    for (int nt = 0; nt < 2; nt++) {
                        uint32_t addr = sB + (uint32_t)p * 10240
                                      + (uint32_t)((wn * 32 + nt * 16 + brow) * 80
                                      + (kk2 * 2 + chalf) * 16);
                        LDMX4(Bfr[p][nt], addr);
                    }
#pragma unroll
                for (int mi = 0; mi < 4; mi++) {
                    uint32_t Afr[3][4];
#pragma unroll
                    for (int p = 0; p < 3; p++) {
                        uint32_t addr = sA + (uint32_t)p * 10240
                                      + (uint32_t)((wm * 64 + mi * 16 + brow) * 80
                                      + (kk2 * 2 + chalf) * 16);
                        LDMX4(Afr[p], addr);
                    }
#pragma unroll
                    for (int c = 0; c < 6; c++) {
#pragma unroll
                        for (int ni = 0; ni < 4; ni++) {
                            uint32_t b0 = Bfr[PB[c]][ni >> 1][ni & 1];
                            uint32_t b1 = Bfr[PB[c]][ni >> 1][2 + (ni & 1)];
                            MMA16816(hacc[mi][ni], Afr[PA[c]], b0, b1);
                        }
                    }
                }
            }
        }

        __syncthreads();
        if (it + 2 < nStages) load_stage(it + 2);
    }

    // ===== epilogues =====
    if (wid < 8) {
        // F: rows m0 + tm*8+i, cols n0 + tn*8..+7 -> fp32 out
        const int col0 = n0 + tn * 8;
        float bv[8];
        *(float4*)&bv[0] = *(const float4*)&bias[col0];
        *(float4*)&bv[4] = *(const float4*)&bias[col0 + 4];
#pragma unroll
        for (int i = 0; i < 8; i++) {
            float v[8];
#pragma unroll
            for (int j = 0; j < 8; j++) {
                float t = facc[i][j] + bv[j];
                if (relu) t = t > 0.f ? t : 0.f;
                v[j] = t;
            }
            float* crow = outF + (size_t)(m0 + tm * 8 + i) * Ng + col0;
            *(float4*)&crow[0] = *(float4*)&v[0];
            *(float4*)&crow[4] = *(float4*)&v[4];
        }
    } else {
        // H: rows m0+128 + wm*64 + (lane>>2) + mi*16 (+8), cols n0+wn*32+(lane&3)*2+ni*8
        const int rbase = m0 + 128 + wm * 64 + (lane >> 2);
        const int cbase = n0 + wn * 32 + (lane & 3) * 2;
#pragma unroll
        for (int mi = 0; mi < 4; mi++) {
#pragma unroll
            for (int ni = 0; ni < 4; ni++) {
                int row = rbase + mi * 16;
                int col = cbase + ni * 8;
                float b0 = bias[col], b1 = bias[col + 1];
                float v00 = hacc[mi][ni][0] + b0, v01 = hacc[mi][ni][1] + b1;
                float v10 = hacc[mi][ni][2] + b0, v11 = hacc[mi][ni][3] + b1;
                if (relu) {
                    v00 = fmaxf(v00, 0.f); v01 = fmaxf(v01, 0.f);
                    v10 = fmaxf(v10, 0.f); v11 = fmaxf(v11, 0.f);
                }
                size_t o0 = (size_t)row * Ng + col;
                size_t o1 = (size_t)(row + 8) * Ng + col;
                if (outp) {
                    __nv_bfloat16 h0, m_0, l0, h1, m_1, l1;
                    split3(v00, h0, m_0, l0); split3(v01, h1, m_1, l1);
                    *(uint32_t*)(outp + o0)         = pk2(h0, h1);
                    *(uint32_t*)(outp + ops + o0)   = pk2(m_0, m_1);
                    *(uint32_t*)(outp + 2*ops + o0) = pk2(l0, l1);
                    split3(v10, h0, m_0, l0); split3(v11, h1, m_1, l1);
                    *(uint32_t*)(outp + o1)         = pk2(h0, h1);
                    *(uint32_t*)(outp + ops + o1)   = pk2(m_0, m_1);
                    *(uint32_t*)(outp + 2*ops + o1) = pk2(l0, l1);
                } else {
                    *(float2*)(outF + o0) = make_float2(v00, v01);
                    *(float2*)(outF + o1) = make_float2(v10, v11);
                }
            }
        }
    }
}

// ===================== fp32 distance path w/ top-2 (R5, verified) ============
__global__ void rownorm256_kernel(const float* __restrict__ X, float* __restrict__ out, int rows)
{
    int gw   = (blockIdx.x * blockDim.x + threadIdx.x) >> 5;
    int lane = threadIdx.x & 31;
    if (gw >= rows) return;
    const float* row = X + (size_t)gw * 256;
    float s = 0.f;
    for (int c = lane * 4; c < 256; c += 128) {
        float4 v = *(const float4*)&row[c];
        s += v.x * v.x + v.y * v.y + v.z * v.z + v.w * v.w;
    }
#pragma unroll
    for (int o = 16; o; o >>= 1) s += __shfl_xor_sync(0xffffffffu, s, o);
    if (!lane) out[gw] = s;
}

__global__ __launch_bounds__(256)
void distmin_kernel(const float* __restrict__ Z, const float* __restrict__ CB,
                    const float* __restrict__ cnorm,
                    float* __restrict__ pval, float* __restrict__ pval2,
                    int* __restrict__ pidx)
{
    const int BM = 128, BN = 128, BK = 16, KD = 256, JG = 1024;
    __shared__ float As[BK][BM];
    __shared__ float Bs[BK][BN];
    __shared__ float s_rv [BM][17];
    __shared__ float s_rv2[BM][17];
    __shared__ int   s_ri [BM][17];
    __shared__ float s_bestv[BM];
    __shared__ float s_bestv2[BM];
    __shared__ int   s_besti[BM];

    const int tid = threadIdx.x;
    const int tm = tid >> 4, tn = tid & 15;
    const int bm  = blockIdx.y;
    const int grp = blockIdx.x;

    if (tid < BM) { s_bestv[tid] = 3.4e38f; s_bestv2[tid] = 3.4e38f; s_besti[tid] = 0; }

    const float* Ablk = Z + (size_t)bm * BM * KD;
    const int t_row = tid >> 2;
    const int t_col = (tid & 3) * 4;

    for (int j0 = grp * JG; j0 < grp * JG + JG; j0 += BN) {
        const float* Bblk = CB + (size_t)j0 * KD;
        float acc[8][8];
#pragma unroll
        for (int i = 0; i < 8; i++)
#pragma unroll
            for (int j = 0; j < 8; j++) acc[i][j] = 0.f;

        float4 pa0, pa1, pb0, pb1;
        pa0 = *(const float4*)(Ablk + (size_t)t_row        * KD + t_col);
        pa1 = *(const float4*)(Ablk + (size_t)(t_row + 64) * KD + t_col);
        pb0 = *(const float4*)(Bblk + (size_t)t_row        * KD + t_col);
        pb1 = *(const float4*)(Bblk + (size_t)(t_row + 64) * KD + t_col);

        for (int k0 = 0; k0 < KD; k0 += BK) {
            __syncthreads();
            As[t_col + 0][t_row]      = pa0.x;
            As[t_col + 1][t_row]      = pa0.y;
            As[t_col + 2][t_row]      = pa0.z;
            As[t_col + 3][t_row]      = pa0.w;
            As[t_col + 0][t_row + 64] = pa1.x;
            As[t_col + 1][t_row + 64] = pa1.y;
            As[t_col + 2][t_row + 64] = pa1.z;
            As[t_col + 3][t_row + 64] = pa1.w;
            Bs[t_col + 0][t_row]      = pb0.x;
            Bs[t_col + 1][t_row]      = pb0.y;
            Bs[t_col + 2][t_row]      = pb0.z;
            Bs[t_col + 3][t_row]      = pb0.w;
            Bs[t_col + 0][t_row + 64] = pb1.x;
            Bs[t_col + 1][t_row + 64] = pb1.y;
            Bs[t_col + 2][t_row + 64] = pb1.z;
            Bs[t_col + 3][t_row + 64] = pb1.w;
            __syncthreads();

            if (k0 + BK < KD) {
                const int kn = k0 + BK;
                pa0 = *(const float4*)(Ablk + (size_t)t_row        * KD + kn + t_col);
                pa1 = *(const float4*)(Ablk + (size_t)(t_row + 64) * KD + kn + t_col);
                pb0 = *(const float4*)(Bblk + (size_t)t_row        * KD + kn + t_col);
                pb1 = *(const float4*)(Bblk + (size_t)(t_row + 64) * KD + kn + t_col);
            }

#pragma unroll
            for (int kk = 0; kk < BK; kk++) {
                float a[8], b[8];
                *(float4*)&a[0] = *(const float4*)&As[kk][tm * 8];
                *(float4*)&a[4] = *(const float4*)&As[kk][tm * 8 + 4];
                *(float4*)&b[0] = *(const float4*)&Bs[kk][tn * 8];
                *(float4*)&b[4] = *(const float4*)&Bs[kk][tn * 8 + 4];
#pragma unroll
                for (int i = 0; i < 8; i++)
#pragma unroll
                    for (int j = 0; j < 8; j++) acc[i][j] += a[i] * b[j];
            }
        }
        __syncthreads();

        float cn[8];
        *(float4*)&cn[0] = *(const float4*)&cnorm[j0 + tn * 8];
        *(float4*)&cn[4] = *(const float4*)&cnorm[j0 + tn * 8 + 4];
#pragma unroll
        for (int i = 0; i < 8; i++) {
            float v1 = 3.4e38f, v2 = 3.4e38f; int i1 = 0;
#pragma unroll
            for (int j = 0; j < 8; j++) {
                float s = cn[j] - 2.f * acc[i][j];
                if (s < v1) { v2 = v1; v1 = s; i1 = j0 + tn * 8 + j; }
                else if (s < v2) v2 = s;
            }
            s_rv [tm * 8 + i][tn] = v1;
            s_rv2[tm * 8 + i][tn] = v2;
            s_ri [tm * 8 + i][tn] = i1;
        }
        __syncthreads();
        if (tid < BM) {
            float V1 = s_bestv[tid], V2 = s_bestv2[tid]; int I1 = s_besti[tid];
#pragma unroll
            for (int t = 0; t < 16; t++) {
                float v1c = s_rv[tid][t], v2c = s_rv2[tid][t];
                if (v1c < V1) { V2 = fminf(V1, v2c); V1 = v1c; I1 = s_ri[tid][t]; }
                else          { V2 = fminf(V2, v1c); }
            }
            s_bestv[tid] = V1; s_bestv2[tid] = V2; s_besti[tid] = I1;
        }
    }
    __syncthreads();
    if (tid < BM) {
        pval [(size_t)grp * NR + bm * BM + tid] = s_bestv[tid];
        pval2[(size_t)grp * NR + bm * BM + tid] = s_bestv2[tid];
        pidx [(size_t)grp * NR + bm * BM + tid] = s_besti[tid];
    }
}

__global__ void zero_flags_kernel() {
    if (threadIdx.x == 0 && blockIdx.x == 0) g_flagcnt = 0;
}

__global__ void combine_kernel(const float* __restrict__ pval, const float* __restrict__ pval2,
                               const int* __restrict__ pidx,
                               const float* __restrict__ znorm,
                               float* __restrict__ minval, int* __restrict__ minidx)
{
    int r = blockIdx.x * blockDim.x + threadIdx.x;
    if (r >= NR) return;
    float V1 = 3.4e38f, V2 = 3.4e38f; int I1 = 0;
#pragma unroll
    for (int g = 0; g < 4; g++) {
        float v1c = pval [(size_t)g * NR + r];
        float v2c = pval2[(size_t)g * NR + r];
        int   i1c = pidx [(size_t)g * NR + r];
        if (v1c < V1) { V2 = fminf(V1, v2c); V1 = v1c; I1 = i1c; }
        else          { V2 = fminf(V2, v1c); }
    }
    float zn = znorm[r];
    minval[r] = zn + V1;
    minidx[r] = I1;
    float d1 = zn + V1, d2 = zn + V2;
    if (d2 - d1 < 1e-4f * (fabsf(d1) + fabsf(d2)) + 1e-3f) {
        int s = atomicAdd(&g_flagcnt, 1);
        if (s < RESCUE_CAP) g_flaglist[s] = r;
    }
}

// ===================== fp32 exact rescue (R5, verified) ======================
__global__ __launch_bounds__(256)
void rescue_kernel(const float* __restrict__ x,
                   const float* __restrict__ W1, const float* __restrict__ b1,
                   const float* __restrict__ W2, const float* __restrict__ b2,
                   const float* __restrict__ W3, const float* __restrict__ b3,
                   const float* __restrict__ CB, const float* __restrict__ cnorm,
                   float* __restrict__ minval, int* __restrict__ minidx)
{
    __shared__ float sx[DIN];
    __shared__ float sh1[DH];
    __shared__ float sh2[DH];
    __shared__ float sz[DZ];
    __shared__ float rv[256];
    __shared__ int   ri[256];

    const int tid = threadIdx.x;
    int cnt = g_flagcnt;
    if (cnt > RESCUE_CAP) cnt = RESCUE_CAP;

    for (int q = blockIdx.x; q < cnt; q += gridDim.x) {
        int r = g_flaglist[q];
        for (int i = tid; i < DIN; i += 256) sx[i] = x[(size_t)r * DIN + i];
        __syncthreads();
        {
            float acc[16];
#pragma unroll
            for (int i = 0; i < 16; i++) acc[i] = b1[tid + 256 * i];
            for (int k = 0; k < DIN; k++) {
                float xv = sx[k];
                const float* wr = W1 + (size_t)k * DH;
#pragma unroll
                for (int i = 0; i < 16; i++) acc[i] += xv * wr[tid + 256 * i];
            }
#pragma unroll
            for (int i = 0; i < 16; i++) sh1[tid + 256 * i] = fmaxf(acc[i], 0.f);
        }
        __syncthreads();
        {
            float acc[16];
#pragma unroll
            for (int i = 0; i < 16; i++) acc[i] = b2[tid + 256 * i];
            for (int k = 0; k < DH; k++) {
                float hv = sh1[k];
                const float* wr = W2 + (size_t)k * DH;
#pragma unroll
                for (int i = 0; i < 16; i++) acc[i] += hv * wr[tid + 256 * i];
            }
#pragma unroll
            for (int i = 0; i < 16; i++) sh2[tid + 256 * i] = acc[i];
        }
        __syncthreads();
        {
            float acc = b3[tid];
            for (int k = 0; k < DH; k++) acc += sh2[k] * W3[(size_t)k * DZ + tid];
            sz[tid] = acc;
        }
        __syncthreads();
        rv[tid] = sz[tid] * sz[tid];
        __syncthreads();
        for (int w = 128; w > 0; w >>= 1) {
            if (tid < w) rv[tid] += rv[tid + w];
            __syncthreads();
        }
        float znorm_r = rv[0];
        __syncthreads();
        {
            float V = 3.4e38f; int I = 0;
            for (int jj = 0; jj < 16; jj++) {
                int j = tid * 16 + jj;
                const float* crow = CB + (size_t)j * DZ;
                float dot = 0.f;
                for (int k = 0; k < DZ; k += 4) {
                    float4 c4 = *(const float4*)(crow + k);
                    dot += sz[k] * c4.x + sz[k+1] * c4.y + sz[k+2] * c4.z + sz[k+3] * c4.w;
                }
                float s = cnorm[j] - 2.f * dot;
                if (s < V) { V = s; I = j; }
            }
            rv[tid] = V; ri[tid] = I;
        }
        __syncthreads();
        for (int w = 128; w > 0; w >>= 1) {
            if (tid < w) {
                if (rv[tid + w] < rv[tid] ||
                    (rv[tid + w] == rv[tid] && ri[tid + w] < ri[tid])) {
                    rv[tid] = rv[tid + w]; ri[tid] = ri[tid + w];
                }
            }
            __syncthreads();
        }
        if (tid == 0) {
            minval[r] = znorm_r + rv[0];
            minidx[r] = ri[0];
        }
        __syncthreads();
    }
}

// ===================== output kernels ========================================
__global__ void gather_kernel(const float* __restrict__ CB, const int* __restrict__ minidx,
                              float* __restrict__ out)
{
    int r = blockIdx.x;
    int c = threadIdx.x;
    float4 v = *(const float4*)&CB[(size_t)minidx[r] * DZ + c * 4];
    *(float4*)&out[(size_t)r * DZ + c * 4] = v;
}

__global__ void loss_kernel(const float* __restrict__ minval, float* __restrict__ out,
                            int out_size)
{
    __shared__ float sm[512];
    int t = threadIdx.x;
    float s = 0.f;
    for (int i = t; i < NR; i += 512) s += minval[i];
    sm[t] = s;
    __syncthreads();
    for (int w = 256; w > 0; w >>= 1) {
        if (t < w) sm[t] += sm[t + w];
        __syncthreads();
    }
    if (t == 0 && out_size > NR * DZ) out[NR * DZ] = 2.f * sm[0];
}

// ===================== launch ================================================
extern "C" void kernel_launch(void* const* d_in, const int* in_sizes, int n_in,
                              void* d_out, int out_size)
{
    const float* x  = (const float*)d_in[0];
    const float* W1 = (const float*)d_in[1];
    const float* b1 = (const float*)d_in[2];
    const float* W2 = (const float*)d_in[3];
    const float* b2 = (const float*)d_in[4];
    const float* W3 = (const float*)d_in[5];
    const float* b3 = (const float*)d_in[6];
    const float* CB = (const float*)d_in[7];
    float* out = (float*)d_out;

    __nv_bfloat16 *xs, *w1s, *w2s, *w3s, *h1s, *h2s;
    float *h1f, *h2f;
    float *z, *znorm, *cnorm, *pval, *pval2, *minval;
    int *pidx, *minidx;
    cudaGetSymbolAddress((void**)&xs,   g_xs);
    cudaGetSymbolAddress((void**)&w1s,  g_w1s);
    cudaGetSymbolAddress((void**)&w2s,  g_w2s);
    cudaGetSymbolAddress((void**)&w3s,  g_w3s);
    cudaGetSymbolAddress((void**)&h1s,  g_h1s);
    cudaGetSymbolAddress((void**)&h2s,  g_h2s);
    cudaGetSymbolAddress((void**)&h1f,  g_h1f);
    cudaGetSymbolAddress((void**)&h2f,  g_h2f);
    cudaGetSymbolAddress((void**)&z,      g_z);
    cudaGetSymbolAddress((void**)&znorm,  g_znorm);
    cudaGetSymbolAddress((void**)&cnorm,  g_cnorm);
    cudaGetSymbolAddress((void**)&pval,   g_pval);
    cudaGetSymbolAddress((void**)&pval2,  g_pval2);
    cudaGetSymbolAddress((void**)&pidx,   g_pidx);
    cudaGetSymbolAddress((void**)&minval, g_minval);
    cudaGetSymbolAddress((void**)&minidx, g_minidx);

    cudaFuncSetAttribute(gemm_hybrid_kernel, cudaFuncAttributeMaxDynamicSharedMemorySize,
                         HYB_SMEM);

    const size_t ps_x  = (size_t)NR * DIN;
    const size_t ps_w1 = (size_t)DH * DIN;
    const size_t ps_w2 = (size_t)DH * DH;
    const size_t ps_w3 = (size_t)DZ * DH;
    const size_t ps_h  = (size_t)NR * DH;

    // splits (limbs; fp32 B comes straight from W, fp32 A from x/h?f)
    split_kernel<<<(unsigned)(ps_x / 4 / 256), 256>>>(x, xs, ps_x, ps_x);
    splitT_kernel<<<dim3(DH / 32, DIN / 32), dim3(32, 8)>>>(W1, w1s, DIN, DH, ps_w1);
    splitT_kernel<<<dim3(DH / 32, DH  / 32), dim3(32, 8)>>>(W2, w2s, DH,  DH, ps_w2);
    splitT_kernel<<<dim3(DZ / 32, DH  / 32), dim3(32, 8)>>>(W3, w3s, DH,  DZ, ps_w3);

    // MLP: warp-specialized dual-pipe GEMMs
    gemm_hybrid_kernel<<<dim3(DH / 128, NR / 256), 512, HYB_SMEM>>>(
        x, xs, ps_x, W1, w1s, ps_w1, b1, h1f, h1s, ps_h, DIN, DH, 1);
    gemm_hybrid_kernel<<<dim3(DH / 128, NR / 256), 512, HYB_SMEM>>>(
        h1f, h1s, ps_h, W2, w2s, ps_w2, b2, h2f, h2s, ps_h, DH, DH, 0);
    gemm_hybrid_kernel<<<dim3(DZ / 128, NR / 256), 512, HYB_SMEM>>>(
        h2f, h2s, ps_h, W3, w3s, ps_w3, b3, z, nullptr, 0, DH, DZ, 0);

    // norms + fused distance/argmin (top-2)
    rownorm256_kernel<<<(KCB * 32) / 256, 256>>>(CB, cnorm, KCB);
    rownorm256_kernel<<<(NR  * 32) / 256, 256>>>(z,  znorm, NR);
    zero_flags_kernel<<<1, 32>>>();
    distmin_kernel<<<dim3(4, NR / 128), 256>>>(z, CB, cnorm, pval, pval2, pidx);
    combine_kernel<<<NR / 256, 256>>>(pval, pval2, pidx, znorm, minval, minidx);

    // exact fp32 rescue for near-tie rows
    rescue_kernel<<<256, 256>>>(x, W1, b1, W2, b2, W3, b3, CB, cnorm, minval, minidx);

    // outputs
    gather_kernel<<<NR, 64>>>(CB, minidx, out);
    loss_kernel<<<1, 512>>>(minval, out, out_size);
}

// round 10
// speedup vs baseline: 1.4499x; 1.4499x over previous
#include <cuda_runtime.h>
#include <cuda_bf16.h>
#include <cstdint>

// Problem constants
#define NR   16384
#define DIN  1024
#define DH   4096
#define DZ   256
#define KCB  4096
#define RESCUE_CAP 4096

// ===================== scratch (device globals) ==============================
__device__ __nv_bfloat16 g_xs [3u * NR * DIN];
__device__ __nv_bfloat16 g_w1s[3u * DH * DIN];
__device__ __nv_bfloat16 g_w2s[3u * DH * DH];
__device__ __nv_bfloat16 g_w3s[3u * DZ * DH];
__device__ __nv_bfloat16 g_h1s[3ull * NR * DH];   // limbs (H rows valid)
__device__ __nv_bfloat16 g_h2s[3ull * NR * DH];
__device__ float g_h1f[(size_t)NR * DH];          // fp32 (F rows valid)
__device__ float g_h2f[(size_t)NR * DH];
__device__ float g_z [NR * DZ];
__device__ float g_znorm[NR];
__device__ float g_cnorm[KCB];
__device__ float g_pval [4 * NR];
__device__ float g_pval2[4 * NR];
__device__ int   g_pidx[4 * NR];
__device__ float g_minval[NR];
__device__ int   g_minidx[NR];
__device__ int   g_flagcnt;
__device__ int   g_flaglist[RESCUE_CAP];

// ===================== helpers ===============================================
__device__ __forceinline__ uint32_t smem_to_u32(const void* smem_ptr) {
    uint32_t addr;
    asm("{ .reg .u64 tmp; cvta.to.shared.u64 tmp, %1; cvt.u32.u64 %0, tmp; }"
        : "=r"(addr) : "l"(smem_ptr));
    return addr;
}
__device__ __forceinline__ void split3(float v, __nv_bfloat16& h, __nv_bfloat16& m,
                                       __nv_bfloat16& l) {
    h = __float2bfloat16(v);
    float r = v - __bfloat162float(h);
    m = __float2bfloat16(r);
    float r2 = r - __bfloat162float(m);
    l = __float2bfloat16(r2);
}
__device__ __forceinline__ uint32_t pk2(__nv_bfloat16 a, __nv_bfloat16 b) {
    return (uint32_t)__bfloat16_as_ushort(a) | ((uint32_t)__bfloat16_as_ushort(b) << 16);
}

#define LDMX4(r, addr) \
    asm volatile("ldmatrix.sync.aligned.m8n8.x4.shared.b16 {%0,%1,%2,%3}, [%4];" \
        : "=r"((r)[0]), "=r"((r)[1]), "=r"((r)[2]), "=r"((r)[3]) : "r"(addr))

#define MMA16816(d, a, b0, b1) \
    asm volatile("mma.sync.aligned.m16n8k16.row.col.f32.bf16.bf16.f32 " \
        "{%0,%1,%2,%3}, {%4,%5,%6,%7}, {%8,%9}, {%0,%1,%2,%3};" \
        : "+f"((d)[0]), "+f"((d)[1]), "+f"((d)[2]), "+f"((d)[3]) \
        : "r"((a)[0]), "r"((a)[1]), "r"((a)[2]), "r"((a)[3]), "r"(b0), "r"(b1))

// ===================== split kernels =========================================
__global__ void split_kernel(const float* __restrict__ in, __nv_bfloat16* __restrict__ out,
                             size_t n, size_t ps)
{
    size_t i = ((size_t)blockIdx.x * blockDim.x + threadIdx.x) * 4;
    if (i >= n) return;
    float4 v = *(const float4*)(in + i);
    __nv_bfloat16 h[4], m[4], l[4];
    split3(v.x, h[0], m[0], l[0]);
    split3(v.y, h[1], m[1], l[1]);
    split3(v.z, h[2], m[2], l[2]);
    split3(v.w, h[3], m[3], l[3]);
    *(uint2*)(out + i)        = make_uint2(pk2(h[0],h[1]), pk2(h[2],h[3]));
    *(uint2*)(out + ps + i)   = make_uint2(pk2(m[0],m[1]), pk2(m[2],m[3]));
    *(uint2*)(out + 2*ps + i) = make_uint2(pk2(l[0],l[1]), pk2(l[2],l[3]));
}

// split + transpose weight W[K][N] fp32 -> out[3][N][K] bf16 limbs
__global__ void splitT_kernel(const float* __restrict__ W, __nv_bfloat16* __restrict__ out,
                              int K, int N, size_t ps)
{
    __shared__ float tile[32][33];
    int k0 = blockIdx.y * 32, n0 = blockIdx.x * 32;
    int tx = threadIdx.x, ty = threadIdx.y;   // 32 x 8
#pragma unroll
    for (int dy = 0; dy < 32; dy += 8)
        tile[ty + dy][tx] = W[(size_t)(k0 + ty + dy) * N + n0 + tx];
    __syncthreads();
#pragma unroll
    for (int dy = 0; dy < 32; dy += 8) {
        int n = n0 + ty + dy, k = k0 + tx;
        float v = tile[tx][ty + dy];
        __nv_bfloat16 h, m, l;
        split3(v, h, m, l);
        size_t off = (size_t)n * K + k;
        out[off]        = h;
        out[ps + off]   = m;
        out[2*ps + off] = l;
    }
}

// ===================== mixed-grid dual-pipe GEMM =============================
// Even row-tiles (blockIdx.y): verbatim R1 fp32 SGEMM body (fma pipe).
// Odd  row-tiles: verbatim R5 bf16x3 mma.sync body, BK=16, pitch 48B (tensor pipe).
// 256 threads, 2 CTAs/SM. H stage: 6 planes x 128 rows x 48B = 36864 B, x2 stages.
#define HPL   6144
#define HSTG  36864
#define MIX_SMEM (2 * HSTG)   // 73728 dynamic (H); F uses its own 16KB static

__global__ __launch_bounds__(256, 2)
void gemm_mixed_kernel(const float* __restrict__ Af,     // fp32 A [M][Kg] (F rows valid)
                       const __nv_bfloat16* __restrict__ Ap, size_t aps,  // A limbs
                       const float* __restrict__ Wf,     // fp32 W [Kg][Ng]
                       const __nv_bfloat16* __restrict__ Bp, size_t bps,  // W^T limbs [N][Kg]
                       const float* __restrict__ bias,
                       float* __restrict__ outF,         // fp32 out (F rows; H too if !outp)
                       __nv_bfloat16* __restrict__ outp, size_t ops,      // limb out (H rows)
                       int Kg, int Ng, int relu)
{
    __shared__ float As[16][128];
    __shared__ float Bs[16][128];
    extern __shared__ char hsm[];

    const int tid = threadIdx.x;
    const int t  = blockIdx.y;
    const int bn = blockIdx.x;
    const int m0 = t * 128;

    if ((t & 1) == 0) {
        // ================= F: exact fp32 (R1 body, verbatim) =================
        const int tm = tid >> 4, tn = tid & 15;
        const float* Ablk = Af + (size_t)m0 * Kg;
        const float* Bblk = Wf + (size_t)bn * 128;

        const int a_row = tid >> 2;
        const int a_col = (tid & 3) * 4;
        const int b_row = tid >> 5;
        const int b_col = (tid & 31) * 4;

        float acc[8][8];
#pragma unroll
        for (int i = 0; i < 8; i++)
#pragma unroll
            for (int j = 0; j < 8; j++) acc[i][j] = 0.f;

        float4 pa0, pa1, pb0, pb1;
        pa0 = *(const float4*)(Ablk + (size_t)a_row        * Kg + a_col);
        pa1 = *(const float4*)(Ablk + (size_t)(a_row + 64) * Kg + a_col);
        pb0 = *(const float4*)(Bblk + (size_t)b_row        * Ng + b_col);
        pb1 = *(const float4*)(Bblk + (size_t)(b_row + 8)  * Ng + b_col);

        for (int k0 = 0; k0 < Kg; k0 += 16) {
            As[a_col + 0][a_row]      = pa0.x;
            As[a_col + 1][a_row]      = pa0.y;
            As[a_col + 2][a_row]      = pa0.z;
            As[a_col + 3][a_row]      = pa0.w;
            As[a_col + 0][a_row + 64] = pa1.x;
            As[a_col + 1][a_row + 64] = pa1.y;
            As[a_col + 2][a_row + 64] = pa1.z;
            As[a_col + 3][a_row + 64] = pa1.w;
            *(float4*)&Bs[b_row][b_col]     = pb0;
            *(float4*)&Bs[b_row + 8][b_col] = pb1;
            __syncthreads();

            if (k0 + 16 < Kg) {
                const int kn = k0 + 16;
                pa0 = *(const float4*)(Ablk + (size_t)a_row        * Kg + kn + a_col);
                pa1 = *(const float4*)(Ablk + (size_t)(a_row + 64) * Kg + kn + a_col);
                pb0 = *(const float4*)(Bblk + (size_t)(kn + b_row)     * Ng + b_col);
                pb1 = *(const float4*)(Bblk + (size_t)(kn + b_row + 8) * Ng + b_col);
            }

#pragma unroll
            for (int kk = 0; kk < 16; kk++) {
                float a[8], b[8];
                *(float4*)&a[0] = *(const float4*)&As[kk][tm * 8];
                *(float4*)&a[4] = *(const float4*)&As[kk][tm * 8 + 4];
                *(float4*)&b[0] = *(const float4*)&Bs[kk][tn * 8];
                *(float4*)&b[4] = *(const float4*)&Bs[kk][tn * 8 + 4];
#pragma unroll
                for (int i = 0; i < 8; i++)
#pragma unroll
                    for (int j = 0; j < 8; j++) acc[i][j] += a[i] * b[j];
            }
            __syncthreads();
        }

        const int row0 = m0 + tm * 8;
        const int col0 = bn * 128 + tn * 8;
        float bv[8];
        *(float4*)&bv[0] = *(const float4*)&bias[col0];
        *(float4*)&bv[4] = *(const float4*)&bias[col0 + 4];
#pragma unroll
        for (int i = 0; i < 8; i++) {
            float v[8];
#pragma unroll
            for (int j = 0; j < 8; j++) {
                float tv = acc[i][j] + bv[j];
                if (relu) tv = tv > 0.f ? tv : 0.f;
                v[j] = tv;
            }
            float* crow = outF + (size_t)(row0 + i) * Ng + col0;
            *(float4*)&crow[0] = *(float4*)&v[0];
            *(float4*)&crow[4] = *(float4*)&v[4];
        }
    } else {
        // ================= H: bf16x3 mma.sync (R5 body, BK=16) ===============
        const uint32_t sb = smem_to_u32(hsm);
        const int wid = tid >> 5, lane = tid & 31;
        const int wm = wid >> 2, wn = wid & 3;
        const int brow  = (lane & 7) + ((lane >> 3) & 1) * 8;
        const int chalf = lane >> 4;
        const int n0 = bn * 128;
        const int nStages = Kg >> 4;

        const __nv_bfloat16* Abase = Ap + (size_t)m0 * Kg;
        const __nv_bfloat16* Bbase = Bp + (size_t)n0 * Kg;

        auto load_stage = [&](int s) {
            const uint32_t dstb = sb + (uint32_t)(s & 1) * HSTG;
            const int k0 = s << 4;
#pragma unroll
            for (int q = 0; q < 6; q++) {
                int id = tid + q * 256;       // 0..1535
                int p = id >> 8;              // plane 0..5
                int rem = id & 255;
                int r = rem >> 1;             // row 0..127
                int c = rem & 1;              // chunk 0..1 (8 bf16 each)
                const __nv_bfloat16* src;
                if (p < 3) src = Abase + (size_t)p * aps + (size_t)r * Kg + k0 + c * 8;
                else       src = Bbase + (size_t)(p - 3) * bps + (size_t)r * Kg + k0 + c * 8;
                uint32_t dst = dstb + (uint32_t)p * HPL + (uint32_t)(r * 48 + c * 16);
                asm volatile("cp.async.cg.shared.global [%0], [%1], 16;"
                             :: "r"(dst), "l"(src) : "memory");
            }
            asm volatile("cp.async.commit_group;" ::: "memory");
        };

        float hacc[4][4][4];
#pragma unroll
        for (int i = 0; i < 4; i++)
#pragma unroll
            for (int j = 0; j < 4; j++)
#pragma unroll
                for (int q = 0; q < 4; q++) hacc[i][j][q] = 0.f;

        const int PA[6] = {0, 0, 1, 0, 2, 1};
        const int PB[6] = {0, 1, 0, 2, 0, 1};

        load_stage(0);
        if (nStages > 1) load_stage(1);

        for (int it = 0; it < nStages; it++) {
            if (it + 1 < nStages) asm volatile("cp.async.wait_group 1;" ::: "memory");
            else                  asm volatile("cp.async.wait_group 0;" ::: "memory");
            __syncthreads();

            const uint32_t sA = sb + (uint32_t)(it & 1) * HSTG;
            const uint32_t sB = sA + 3 * HPL;

            uint32_t Bfr[3][2][4];
#pragma unroll
            for (int p = 0; p < 3; p++)
#pragma unroll
                for (int nt = 0; nt < 2; nt++) {
                    uint32_t addr = sB + (uint32_t)p * HPL
                                  + (uint32_t)((wn * 32 + nt * 16 + brow) * 48 + chalf * 16);
                    LDMX4(Bfr[p][nt], addr);
                }
#pragma unroll
            for (int mi = 0; mi < 4; mi++) {
                uint32_t Afr[3][4];
#pragma unroll
                for (int p = 0; p < 3; p++) {
                    uint32_t addr = sA + (uint32_t)p * HPL
                                  + (uint32_t)((wm * 64 + mi * 16 + brow) * 48 + chalf * 16);
                    LDMX4(Afr[p], addr);
                }
#pragma unroll
                for (int c = 0; c < 6; c++) {
#pragma unroll
                    for (int ni = 0; ni < 4; ni++) {
                        uint32_t b0 = Bfr[PB[c]][ni >> 1][ni & 1];
                        uint32_t b1 = Bfr[PB[c]][ni >> 1][2 + (ni & 1)];
                        MMA16816(hacc[mi][ni], Afr[PA[c]], b0, b1);
                    }
                }
            }

            __syncthreads();
            if (it + 2 < nStages) load_stage(it + 2);
        }

        // H epilogue
        const int rbase = m0 + wm * 64 + (lane >> 2);
        const int cbase = n0 + wn * 32 + (lane & 3) * 2;
#pragma unroll
        for (int mi = 0; mi < 4; mi++) {
#pragma unroll
            for (int ni = 0; ni < 4; ni++) {
                int row = rbase + mi * 16;
                int col = cbase + ni * 8;
                float b0 = bias[col], b1 = bias[col + 1];
                float v00 = hacc[mi][ni][0] + b0, v01 = hacc[mi][ni][1] + b1;
                float v10 = hacc[mi][ni][2] + b0, v11 = hacc[mi][ni][3] + b1;
                if (relu) {
                    v00 = fmaxf(v00, 0.f); v01 = fmaxf(v01, 0.f);
                    v10 = fmaxf(v10, 0.f); v11 = fmaxf(v11, 0.f);
                }
                size_t o0 = (size_t)row * Ng + col;
                size_t o1 = (size_t)(row + 8) * Ng + col;
                if (outp) {
                    __nv_bfloat16 h0, m_0, l0, h1, m_1, l1;
                    split3(v00, h0, m_0, l0); split3(v01, h1, m_1, l1);
                    *(uint32_t*)(outp + o0)         = pk2(h0, h1);
                    *(uint32_t*)(outp + ops + o0)   = pk2(m_0, m_1);
                    *(uint32_t*)(outp + 2*ops + o0) = pk2(l0, l1);
                    split3(v10, h0, m_0, l0); split3(v11, h1, m_1, l1);
                    *(uint32_t*)(outp + o1)         = pk2(h0, h1);
                    *(uint32_t*)(outp + ops + o1)   = pk2(m_0, m_1);
                    *(uint32_t*)(outp + 2*ops + o1) = pk2(l0, l1);
                } else {
                    *(float2*)(outF + o0) = make_float2(v00, v01);
                    *(float2*)(outF + o1) = make_float2(v10, v11);
                }
            }
        }
    }
}

// ===================== fp32 distance path w/ top-2 (R5, verified) ============
__global__ void rownorm256_kernel(const float* __restrict__ X, float* __restrict__ out, int rows)
{
    int gw   = (blockIdx.x * blockDim.x + threadIdx.x) >> 5;
    int lane = threadIdx.x & 31;
    if (gw >= rows) return;
    const float* row = X + (size_t)gw * 256;
    float s = 0.f;
    for (int c = lane * 4; c < 256; c += 128) {
        float4 v = *(const float4*)&row[c];
        s += v.x * v.x + v.y * v.y + v.z * v.z + v.w * v.w;
    }
#pragma unroll
    for (int o = 16; o; o >>= 1) s += __shfl_xor_sync(0xffffffffu, s, o);
    if (!lane) out[gw] = s;
}

__global__ __launch_bounds__(256)
void distmin_kernel(const float* __restrict__ Z, const float* __restrict__ CB,
                    const float* __restrict__ cnorm,
                    float* __restrict__ pval, float* __restrict__ pval2,
                    int* __restrict__ pidx)
{
    const int BM = 128, BN = 128, BK = 16, KD = 256, JG = 1024;
    __shared__ float As[BK][BM];
    __shared__ float Bs[BK][BN];
    __shared__ float s_rv [BM][17];
    __shared__ float s_rv2[BM][17];
    __shared__ int   s_ri [BM][17];
    __shared__ float s_bestv[BM];
    __shared__ float s_bestv2[BM];
    __shared__ int   s_besti[BM];

    const int tid = threadIdx.x;
    const int tm = tid >> 4, tn = tid & 15;
    const int bm  = blockIdx.y;
    const int grp = blockIdx.x;

    if (tid < BM) { s_bestv[tid] = 3.4e38f; s_bestv2[tid] = 3.4e38f; s_besti[tid] = 0; }

    const float* Ablk = Z + (size_t)bm * BM * KD;
    const int t_row = tid >> 2;
    const int t_col = (tid & 3) * 4;

    for (int j0 = grp * JG; j0 < grp * JG + JG; j0 += BN) {
        const float* Bblk = CB + (size_t)j0 * KD;
        float acc[8][8];
#pragma unroll
        for (int i = 0; i < 8; i++)
#pragma unroll
            for (int j = 0; j < 8; j++) acc[i][j] = 0.f;

        float4 pa0, pa1, pb0, pb1;
        pa0 = *(const float4*)(Ablk + (size_t)t_row        * KD + t_col);
        pa1 = *(const float4*)(Ablk + (size_t)(t_row + 64) * KD + t_col);
        pb0 = *(const float4*)(Bblk + (size_t)t_row        * KD + t_col);
        pb1 = *(const float4*)(Bblk + (size_t)(t_row + 64) * KD + t_col);

        for (int k0 = 0; k0 < KD; k0 += BK) {
            __syncthreads();
            As[t_col + 0][t_row]      = pa0.x;
            As[t_col + 1][t_row]      = pa0.y;
            As[t_col + 2][t_row]      = pa0.z;
            As[t_col + 3][t_row]      = pa0.w;
            As[t_col + 0][t_row + 64] = pa1.x;
            As[t_col + 1][t_row + 64] = pa1.y;
            As[t_col + 2][t_row + 64] = pa1.z;
            As[t_col + 3][t_row + 64] = pa1.w;
            Bs[t_col + 0][t_row]      = pb0.x;
            Bs[t_col + 1][t_row]      = pb0.y;
            Bs[t_col + 2][t_row]      = pb0.z;
            Bs[t_col + 3][t_row]      = pb0.w;
            Bs[t_col + 0][t_row + 64] = pb1.x;
            Bs[t_col + 1][t_row + 64] = pb1.y;
            Bs[t_col + 2][t_row + 64] = pb1.z;
            Bs[t_col + 3][t_row + 64] = pb1.w;
            __syncthreads();

            if (k0 + BK < KD) {
                const int kn = k0 + BK;
                pa0 = *(const float4*)(Ablk + (size_t)t_row        * KD + kn + t_col);
                pa1 = *(const float4*)(Ablk + (size_t)(t_row + 64) * KD + kn + t_col);
                pb0 = *(const float4*)(Bblk + (size_t)t_row        * KD + kn + t_col);
                pb1 = *(const float4*)(Bblk + (size_t)(t_row + 64) * KD + kn + t_col);
            }

#pragma unroll
            for (int kk = 0; kk < BK; kk++) {
                float a[8], b[8];
                *(float4*)&a[0] = *(const float4*)&As[kk][tm * 8];
                *(float4*)&a[4] = *(const float4*)&As[kk][tm * 8 + 4];
                *(float4*)&b[0] = *(const float4*)&Bs[kk][tn * 8];
                *(float4*)&b[4] = *(const float4*)&Bs[kk][tn * 8 + 4];
#pragma unroll
                for (int i = 0; i < 8; i++)
#pragma unroll
                    for (int j = 0; j < 8; j++) acc[i][j] += a[i] * b[j];
            }
        }
        __syncthreads();

        float cn[8];
        *(float4*)&cn[0] = *(const float4*)&cnorm[j0 + tn * 8];
        *(float4*)&cn[4] = *(const float4*)&cnorm[j0 + tn * 8 + 4];
#pragma unroll
        for (int i = 0; i < 8; i++) {
            float v1 = 3.4e38f, v2 = 3.4e38f; int i1 = 0;
#pragma unroll
            for (int j = 0; j < 8; j++) {
                float s = cn[j] - 2.f * acc[i][j];
                if (s < v1) { v2 = v1; v1 = s; i1 = j0 + tn * 8 + j; }
                else if (s < v2) v2 = s;
            }
            s_rv [tm * 8 + i][tn] = v1;
            s_rv2[tm * 8 + i][tn] = v2;
            s_ri [tm * 8 + i][tn] = i1;
        }
        __syncthreads();
        if (tid < BM) {
            float V1 = s_bestv[tid], V2 = s_bestv2[tid]; int I1 = s_besti[tid];
#pragma unroll
            for (int q = 0; q < 16; q++) {
                float v1c = s_rv[tid][q], v2c = s_rv2[tid][q];
                if (v1c < V1) { V2 = fminf(V1, v2c); V1 = v1c; I1 = s_ri[tid][q]; }
                else          { V2 = fminf(V2, v1c); }
            }
            s_bestv[tid] = V1; s_bestv2[tid] = V2; s_besti[tid] = I1;
        }
    }
    __syncthreads();
    if (tid < BM) {
        pval [(size_t)grp * NR + bm * BM + tid] = s_bestv[tid];
        pval2[(size_t)grp * NR + bm * BM + tid] = s_bestv2[tid];
        pidx [(size_t)grp * NR + bm * BM + tid] = s_besti[tid];
    }
}

__global__ void zero_flags_kernel() {
    if (threadIdx.x == 0 && blockIdx.x == 0) g_flagcnt = 0;
}

__global__ void combine_kernel(const float* __restrict__ pval, const float* __restrict__ pval2,
                               const int* __restrict__ pidx,
                               const float* __restrict__ znorm,
                               float* __restrict__ minval, int* __restrict__ minidx)
{
    int r = blockIdx.x * blockDim.x + threadIdx.x;
    if (r >= NR) return;
    float V1 = 3.4e38f, V2 = 3.4e38f; int I1 = 0;
#pragma unroll
    for (int g = 0; g < 4; g++) {
        float v1c = pval [(size_t)g * NR + r];
        float v2c = pval2[(size_t)g * NR + r];
        int   i1c = pidx [(size_t)g * NR + r];
        if (v1c < V1) { V2 = fminf(V1, v2c); V1 = v1c; I1 = i1c; }
        else          { V2 = fminf(V2, v1c); }
    }
    float zn = znorm[r];
    minval[r] = zn + V1;
    minidx[r] = I1;
    float d1 = zn + V1, d2 = zn + V2;
    if (d2 - d1 < 1e-4f * (fabsf(d1) + fabsf(d2)) + 1e-3f) {
        int s = atomicAdd(&g_flagcnt, 1);
        if (s < RESCUE_CAP) g_flaglist[s] = r;
    }
}

// ===================== fp32 exact rescue (R5, verified) ======================
__global__ __launch_bounds__(256)
void rescue_kernel(const float* __restrict__ x,
                   const float* __restrict__ W1, const float* __restrict__ b1,
                   const float* __restrict__ W2, const float* __restrict__ b2,
                   const float* __restrict__ W3, const float* __restrict__ b3,
                   const float* __restrict__ CB, const float* __restrict__ cnorm,
                   float* __restrict__ minval, int* __restrict__ minidx)
{
    __shared__ float sx[DIN];
    __shared__ float sh1[DH];
    __shared__ float sh2[DH];
    __shared__ float sz[DZ];
    __shared__ float rv[256];
    __shared__ int   ri[256];

    const int tid = threadIdx.x;
    int cnt = g_flagcnt;
    if (cnt > RESCUE_CAP) cnt = RESCUE_CAP;

    for (int q = blockIdx.x; q < cnt; q += gridDim.x) {
        int r = g_flaglist[q];
        for (int i = tid; i < DIN; i += 256) sx[i] = x[(size_t)r * DIN + i];
        __syncthreads();
        {
            float acc[16];
#pragma unroll
            for (int i = 0; i < 16; i++) acc[i] = b1[tid + 256 * i];
            for (int k = 0; k < DIN; k++) {
                float xv = sx[k];
                const float* wr = W1 + (size_t)k * DH;
#pragma unroll
                for (int i = 0; i < 16; i++) acc[i] += xv * wr[tid + 256 * i];
            }
#pragma unroll
            for (int i = 0; i < 16; i++) sh1[tid + 256 * i] = fmaxf(acc[i], 0.f);
        }
        __syncthreads();
        {
            float acc[16];
#pragma unroll
            for (int i = 0; i < 16; i++) acc[i] = b2[tid + 256 * i];
            for (int k = 0; k < DH; k++) {
                float hv = sh1[k];
                const float* wr = W2 + (size_t)k * DH;
#pragma unroll
                for (int i = 0; i < 16; i++) acc[i] += hv * wr[tid + 256 * i];
            }
#pragma unroll
            for (int i = 0; i < 16; i++) sh2[tid + 256 * i] = acc[i];
        }
        __syncthreads();
        {
            float acc = b3[tid];
            for (int k = 0; k < DH; k++) acc += sh2[k] * W3[(size_t)k * DZ + tid];
            sz[tid] = acc;
        }
        __syncthreads();
        rv[tid] = sz[tid] * sz[tid];
        __syncthreads();
        for (int w = 128; w > 0; w >>= 1) {
            if (tid < w) rv[tid] += rv[tid + w];
            __syncthreads();
        }
        float znorm_r = rv[0];
        __syncthreads();
        {
            float V = 3.4e38f; int I = 0;
            for (int jj = 0; jj < 16; jj++) {
                int j = tid * 16 + jj;
                const float* crow = CB + (size_t)j * DZ;
                float dot = 0.f;
                for (int k = 0; k < DZ; k += 4) {
                    float4 c4 = *(const float4*)(crow + k);
                    dot += sz[k] * c4.x + sz[k+1] * c4.y + sz[k+2] * c4.z + sz[k+3] * c4.w;
                }
                float s = cnorm[j] - 2.f * dot;
                if (s < V) { V = s; I = j; }
            }
            rv[tid] = V; ri[tid] = I;
        }
        __syncthreads();
        for (int w = 128; w > 0; w >>= 1) {
            if (tid < w) {
                if (rv[tid + w] < rv[tid] ||
                    (rv[tid + w] == rv[tid] && ri[tid + w] < ri[tid])) {
                    rv[tid] = rv[tid + w]; ri[tid] = ri[tid + w];
                }
            }
            __syncthreads();
        }
        if (tid == 0) {
            minval[r] = znorm_r + rv[0];
            minidx[r] = ri[0];
        }
        __syncthreads();
    }
}

// ===================== output kernels ========================================
__global__ void gather_kernel(const float* __restrict__ CB, const int* __restrict__ minidx,
                              float* __restrict__ out)
{
    int r = blockIdx.x;
    int c = threadIdx.x;
    float4 v = *(const float4*)&CB[(size_t)minidx[r] * DZ + c * 4];
    *(float4*)&out[(size_t)r * DZ + c * 4] = v;
}

__global__ void loss_kernel(const float* __restrict__ minval, float* __restrict__ out,
                            int out_size)
{
    __shared__ float sm[512];
    int t = threadIdx.x;
    float s = 0.f;
    for (int i = t; i < NR; i += 512) s += minval[i];
    sm[t] = s;
    __syncthreads();
    for (int w = 256; w > 0; w >>= 1) {
        if (t < w) sm[t] += sm[t + w];
        __syncthreads();
    }
    if (t == 0 && out_size > NR * DZ) out[NR * DZ] = 2.f * sm[0];
}

// ===================== launch ================================================
extern "C" void kernel_launch(void* const* d_in, const int* in_sizes, int n_in,
                              void* d_out, int out_size)
{
    const float* x  = (const float*)d_in[0];
    const float* W1 = (const float*)d_in[1];
    const float* b1 = (const float*)d_in[2];
    const float* W2 = (const float*)d_in[3];
    const float* b2 = (const float*)d_in[4];
    const float* W3 = (const float*)d_in[5];
    const float* b3 = (const float*)d_in[6];
    const float* CB = (const float*)d_in[7];
    float* out = (float*)d_out;

    __nv_bfloat16 *xs, *w1s, *w2s, *w3s, *h1s, *h2s;
    float *h1f, *h2f;
    float *z, *znorm, *cnorm, *pval, *pval2, *minval;
    int *pidx, *minidx;
    cudaGetSymbolAddress((void**)&xs,   g_xs);
    cudaGetSymbolAddress((void**)&w1s,  g_w1s);
    cudaGetSymbolAddress((void**)&w2s,  g_w2s);
    cudaGetSymbolAddress((void**)&w3s,  g_w3s);
    cudaGetSymbolAddress((void**)&h1s,  g_h1s);
    cudaGetSymbolAddress((void**)&h2s,  g_h2s);
    cudaGetSymbolAddress((void**)&h1f,  g_h1f);
    cudaGetSymbolAddress((void**)&h2f,  g_h2f);
    cudaGetSymbolAddress((void**)&z,      g_z);
    cudaGetSymbolAddress((void**)&znorm,  g_znorm);
    cudaGetSymbolAddress((void**)&cnorm,  g_cnorm);
    cudaGetSymbolAddress((void**)&pval,   g_pval);
    cudaGetSymbolAddress((void**)&pval2,  g_pval2);
    cudaGetSymbolAddress((void**)&pidx,   g_pidx);
    cudaGetSymbolAddress((void**)&minval, g_minval);
    cudaGetSymbolAddress((void**)&minidx, g_minidx);

    cudaFuncSetAttribute(gemm_mixed_kernel, cudaFuncAttributeMaxDynamicSharedMemorySize,
                         MIX_SMEM);

    const size_t ps_x  = (size_t)NR * DIN;
    const size_t ps_w1 = (size_t)DH * DIN;
    const size_t ps_w2 = (size_t)DH * DH;
    const size_t ps_w3 = (size_t)DZ * DH;
    const size_t ps_h  = (size_t)NR * DH;

    // limb splits (H path inputs)
    split_kernel<<<(unsigned)(ps_x / 4 / 256), 256>>>(x, xs, ps_x, ps_x);
    splitT_kernel<<<dim3(DH / 32, DIN / 32), dim3(32, 8)>>>(W1, w1s, DIN, DH, ps_w1);
    splitT_kernel<<<dim3(DH / 32, DH  / 32), dim3(32, 8)>>>(W2, w2s, DH,  DH, ps_w2);
    splitT_kernel<<<dim3(DZ / 32, DH  / 32), dim3(32, 8)>>>(W3, w3s, DH,  DZ, ps_w3);

    // MLP: mixed-grid dual-pipe GEMMs (even tiles fp32, odd tiles bf16x3)
    gemm_mixed_kernel<<<dim3(DH / 128, NR / 128), 256, MIX_SMEM>>>(
        x, xs, ps_x, W1, w1s, ps_w1, b1, h1f, h1s, ps_h, DIN, DH, 1);
    gemm_mixed_kernel<<<dim3(DH / 128, NR / 128), 256, MIX_SMEM>>>(
        h1f, h1s, ps_h, W2, w2s, ps_w2, b2, h2f, h2s, ps_h, DH, DH, 0);
    gemm_mixed_kernel<<<dim3(DZ / 128, NR / 128), 256, MIX_SMEM>>>(
        h2f, h2s, ps_h, W3, w3s, ps_w3, b3, z, nullptr, 0, DH, DZ, 0);

    // norms + fused distance/argmin (top-2)
    rownorm256_kernel<<<(KCB * 32) / 256, 256>>>(CB, cnorm, KCB);
    rownorm256_kernel<<<(NR  * 32) / 256, 256>>>(z,  znorm, NR);
    zero_flags_kernel<<<1, 32>>>();
    distmin_kernel<<<dim3(4, NR / 128), 256>>>(z, CB, cnorm, pval, pval2, pidx);
    combine_kernel<<<NR / 256, 256>>>(pval, pval2, pidx, znorm, minval, minidx);

    // exact fp32 rescue for near-tie rows
    rescue_kernel<<<256, 256>>>(x, W1, b1, W2, b2, W3, b3, CB, cnorm, minval, minidx);

    // outputs
    gather_kernel<<<NR, 64>>>(CB, minidx, out);
    loss_kernel<<<1, 512>>>(minval, out, out_size);
}